// round 7
// baseline (speedup 1.0000x reference)
#include <cuda_runtime.h>

#define TT 2048
#define BB 32
#define HH 256
#define G4H 1024
#define GRID_R 128

// ---------------- scratch (static device allocations; no cudaMalloc) ----------------
__device__ float g_xg[(size_t)TT * G4H * BB];   // [t][gate_row][b]  256 MB
__device__ float g_hs0[(size_t)TT * BB * HH];   // layer-0 hidden outputs, 64 MB
__device__ float g_hbuf[2][BB * HH];            // double-buffered h state [buf][b][j]
__device__ unsigned g_ctrs[2][8 * 32];          // distributed arrival counters (128B apart)
__device__ unsigned g_epoch[2][32];             // broadcast epoch flag (padded line)
__device__ unsigned g_done[2];                  // per-layer reset handshake
__device__ int g_len[BB];                       // normalized lengths (int32)

// strong-memory helpers (gpu scope)
__device__ __forceinline__ void arrive_release(unsigned* p) {
    asm volatile("red.release.gpu.global.add.u32 [%0], %1;" :: "l"(p), "r"(1u) : "memory");
}
__device__ __forceinline__ unsigned ld_acquire(const unsigned* p) {
    unsigned v;
    asm volatile("ld.acquire.gpu.global.u32 %0, [%1];" : "=r"(v) : "l"(p) : "memory");
    return v;
}
__device__ __forceinline__ void st_release(unsigned* p, unsigned v) {
    asm volatile("st.release.gpu.global.u32 [%0], %1;" :: "l"(p), "r"(v) : "memory");
}

// ---------------- lengths normalization: handles int32 OR int64 input buffer ----------
__global__ void norm_lengths(const int* __restrict__ lenw)
{
    int i = threadIdx.x;            // 0..31
    int is64 = (lenw[1] == 0);
    int v = is64 ? lenw[2 * i] : lenw[i];
    g_len[i] = v;
}

// ---------------- input-projection GEMM: out[t][row][b] = X @ W^T + bias ----------------
// X: [T*B][256] row-major, W: [1024][256], out: [T][1024][32]
__global__ __launch_bounds__(256) void xg_gemm(const float* __restrict__ X,
                                               const float* __restrict__ W,
                                               const float* __restrict__ bias,
                                               float* __restrict__ out)
{
    __shared__ float xs[64][65];
    __shared__ float ws[64][65];
    const int tid = threadIdx.x;
    const int tx = tid & 15;        // tb quad
    const int ty = tid >> 4;        // row quad
    const int tb0 = blockIdx.x * 64;
    const int r0 = blockIdx.y * 64;
    const int lrow = tid >> 4;      // load row 0..15 (x4 passes)
    const int lkq = tid & 15;       // load k-quad

    float acc[4][4];
#pragma unroll
    for (int i = 0; i < 4; i++)
#pragma unroll
        for (int j = 0; j < 4; j++) acc[i][j] = 0.f;

    for (int kt = 0; kt < 256; kt += 64) {
#pragma unroll
        for (int p = 0; p < 4; p++) {
            int row = lrow + p * 16;
            float4 xv = *(const float4*)&X[(size_t)(tb0 + row) * 256 + kt + lkq * 4];
            xs[row][lkq * 4 + 0] = xv.x; xs[row][lkq * 4 + 1] = xv.y;
            xs[row][lkq * 4 + 2] = xv.z; xs[row][lkq * 4 + 3] = xv.w;
            float4 wv = *(const float4*)&W[(size_t)(r0 + row) * 256 + kt + lkq * 4];
            ws[row][lkq * 4 + 0] = wv.x; ws[row][lkq * 4 + 1] = wv.y;
            ws[row][lkq * 4 + 2] = wv.z; ws[row][lkq * 4 + 3] = wv.w;
        }
        __syncthreads();
#pragma unroll 8
        for (int k = 0; k < 64; k++) {
            float xf[4], wf[4];
#pragma unroll
            for (int j = 0; j < 4; j++) xf[j] = xs[tx * 4 + j][k];
#pragma unroll
            for (int i = 0; i < 4; i++) wf[i] = ws[ty * 4 + i][k];
#pragma unroll
            for (int i = 0; i < 4; i++)
#pragma unroll
                for (int j = 0; j < 4; j++) acc[i][j] += wf[i] * xf[j];
        }
        __syncthreads();
    }

    const int tbb = tb0 + tx * 4;
    const int t = tbb >> 5;
    const int b0 = tbb & 31;
#pragma unroll
    for (int i = 0; i < 4; i++) {
        int row = r0 + ty * 4 + i;
        float bv = bias[row];
        float4 v = make_float4(acc[i][0] + bv, acc[i][1] + bv, acc[i][2] + bv, acc[i][3] + bv);
        *(float4*)&out[(size_t)t * 32768 + row * 32 + b0] = v;
    }
}

// ---------------- persistent recurrent kernel (one layer) ----------------
// 128 threads: b = tid&31, w = tid>>5 (0..3). Thread computes rows q=w and q=w+4
// (q -> gate = q>>1, u = q&1). CTA owns units {2*bid, 2*bid+1}; 128 CTAs.
// Barrier: distributed release-arrivals + single aggregator (CTA 0) publishing an
// epoch flag with release; followers acquire-poll the epoch. Formally strong chain.
__global__ __launch_bounds__(128) void lstm_rec(
    const int layer,
    const float* __restrict__ h0,        // [B][H] slice for this layer
    const float* __restrict__ c0,
    const float* __restrict__ Whh,       // [1024][256]
    float* __restrict__ hs_out,          // [T][B][H]
    float* __restrict__ cs_out,          // [T][B][H] or nullptr
    float* __restrict__ hT_out,          // [B][H]
    float* __restrict__ cT_out)
{
    __shared__ float4 w4s[8 * 64];        // 8 gate rows x 256 k (float4)
    __shared__ float4 h4s[32 * 65];       // h staged [b][k4], pitch 65 -> conflict-free
    __shared__ float gsm[8][33];          // gate exchange

    const int tid = threadIdx.x;
    const int b = tid & 31;
    const int w = tid >> 5;               // 0..3
    const int bid = blockIdx.x;
    const int row0 = (w >> 1) * 256 + bid * 2 + (w & 1);
    const int row1 = row0 + 512;

    // load this CTA's 8 W_hh rows into smem (once)
    {
        const float4* W4 = (const float4*)Whh;
#pragma unroll
        for (int p = 0; p < 4; p++) {
            int i = tid + p * 128;        // 0..511
            int qq = i >> 6, k4 = i & 63;
            int rr = (qq >> 1) * 256 + bid * 2 + (qq & 1);
            w4s[i] = W4[(size_t)rr * 64 + k4];
        }
    }

    // state owners: tid < 64 -> (u = tid>>5, b)
    float c_reg = 0.f, h_reg = 0.f;
    int len_b = 0;
    const int j_own = bid * 2 + (tid >> 5);   // valid for tid<64
    if (tid < 64) {
        h_reg = h0[b * 256 + j_own];
        c_reg = c0[b * 256 + j_own];
        len_b = g_len[b];
        __stcg(&g_hbuf[0][b * 256 + j_own], h_reg);
    }
    __threadfence();
    __syncthreads();
    if (tid == 0) arrive_release(&g_ctrs[layer][(bid & 7) * 32]);

    unsigned target = GRID_R;

    for (int t = 0; t < TT; t++) {
        // prefetch xg (independent of barrier) to hide DRAM latency behind sync
        float xg0 = __ldg(&g_xg[(size_t)t * 32768 + row0 * 32 + b]);
        float xg1 = __ldg(&g_xg[(size_t)t * 32768 + row1 * 32 + b]);

        if (tid == 0) {
            if (bid == 0) {
                // aggregator: sum 8 counters (acquire loads), publish epoch (release)
                unsigned* cp = &g_ctrs[layer][0];
                unsigned s;
                do {
                    unsigned v0 = ld_acquire(cp + 0 * 32);
                    unsigned v1 = ld_acquire(cp + 1 * 32);
                    unsigned v2 = ld_acquire(cp + 2 * 32);
                    unsigned v3 = ld_acquire(cp + 3 * 32);
                    unsigned v4 = ld_acquire(cp + 4 * 32);
                    unsigned v5 = ld_acquire(cp + 5 * 32);
                    unsigned v6 = ld_acquire(cp + 6 * 32);
                    unsigned v7 = ld_acquire(cp + 7 * 32);
                    s = v0 + v1 + v2 + v3 + v4 + v5 + v6 + v7;
                } while (s < target);
                st_release(&g_epoch[layer][0], (unsigned)(t + 1));
            } else {
                // follower: acquire-poll the read-only epoch flag
                while (ld_acquire(&g_epoch[layer][0]) < (unsigned)(t + 1)) { }
            }
            __threadfence();
        }
        __syncthreads();
        target += GRID_R;

        // stage full h into smem (L2-coherent loads; cross-SM producer)
        {
            const float4* hb = (const float4*)g_hbuf[t & 1];
#pragma unroll
            for (int p = 0; p < 16; p++) {
                int i = tid + p * 128;    // 0..2047
                h4s[(i >> 6) * 65 + (i & 63)] = __ldcg(&hb[i]);
            }
        }
        __syncthreads();

        // dot: two rows per thread, hv reused; wv loads are warp-broadcast
        float a0 = 0.f, a1 = 0.f;
        {
            const float4* hr = &h4s[b * 65];
            const float4* w0 = &w4s[w * 64];
            const float4* w1 = &w4s[(w + 4) * 64];
#pragma unroll 16
            for (int k4 = 0; k4 < 64; k4++) {
                float4 hv = hr[k4];
                float4 v0 = w0[k4];
                float4 v1 = w1[k4];
                a0 += hv.x * v0.x; a0 += hv.y * v0.y;
                a0 += hv.z * v0.z; a0 += hv.w * v0.w;
                a1 += hv.x * v1.x; a1 += hv.y * v1.y;
                a1 += hv.z * v1.z; a1 += hv.w * v1.w;
            }
        }
        gsm[w][b] = a0 + xg0;
        gsm[w + 4][b] = a1 + xg1;
        __syncthreads();

        if (tid < 64) {
            int u = tid >> 5;
            float gi = gsm[0 + u][b];
            float gf = gsm[2 + u][b];
            float gg = gsm[4 + u][b];
            float go = gsm[6 + u][b];
            float i_ = 1.f / (1.f + __expf(-gi));
            float f_ = 1.f / (1.f + __expf(-gf));
            float g_ = tanhf(gg);
            float o_ = 1.f / (1.f + __expf(-go));
            float cn = f_ * c_reg + i_ * g_;
            float hn = o_ * tanhf(cn);
            if (t < len_b) { c_reg = cn; h_reg = hn; }
            int oidx = t * 8192 + b * 256 + j_own;
            hs_out[oidx] = h_reg;
            if (cs_out) cs_out[oidx] = c_reg;
            __stcg(&g_hbuf[(t + 1) & 1][b * 256 + j_own], h_reg);
            __threadfence();
        }
        __syncthreads();
        if (tid == 0) arrive_release(&g_ctrs[layer][(bid & 7) * 32]);
    }

    if (tid < 64) {
        hT_out[b * 256 + j_own] = h_reg;
        cT_out[b * 256 + j_own] = c_reg;
    }

    // reset handshake so graph replays start from clean counters.
    // CRITICAL: fence between the final arrival atomic (above) and the g_done
    // atomic, so the resetter cannot zero the counters while a straggler's
    // last +1 is still in flight (cross-L2-slice visibility race).
    __syncthreads();
    if (tid == 0) {
        __threadfence();
        unsigned d = atomicAdd(&g_done[layer], 1);
        if (d == GRID_R - 1) {
#pragma unroll
            for (int i = 0; i < 8; i++) g_ctrs[layer][i * 32] = 0;
            g_epoch[layer][0] = 0;
            __threadfence();
            g_done[layer] = 0;
        }
    }
}

// ---------------- launch ----------------
extern "C" void kernel_launch(void* const* d_in, const int* in_sizes, int n_in,
                              void* d_out, int out_size)
{
    const float* x        = (const float*)d_in[0];
    const int*   lenw     = (const int*)d_in[1];   // dtype detected on device
    const float* h0       = (const float*)d_in[2];
    const float* c0       = (const float*)d_in[3];
    const float* Wih0     = (const float*)d_in[4];
    const float* Whh0     = (const float*)d_in[5];
    const float* b0v      = (const float*)d_in[6];
    const float* Wih1     = (const float*)d_in[7];
    const float* Whh1     = (const float*)d_in[8];
    const float* b1v      = (const float*)d_in[9];
    float* out = (float*)d_out;

    float* xg_p = nullptr;
    float* hs0_p = nullptr;
    cudaGetSymbolAddress((void**)&xg_p, g_xg);
    cudaGetSymbolAddress((void**)&hs0_p, g_hs0);

    const size_t SEQ = (size_t)TT * BB * HH;   // 16,777,216
    float* hs_final = out;                     // [T][B][H]
    float* cs_final = out + SEQ;               // [T][B][H]
    float* hT = out + 2 * SEQ;                 // [2][B][H]
    float* cT = out + 2 * SEQ + 2 * BB * HH;   // [2][B][H]

    dim3 ggrid(1024, 16);

    norm_lengths<<<1, 32>>>(lenw);

    // layer 0
    xg_gemm<<<ggrid, 256>>>(x, Wih0, b0v, xg_p);
    lstm_rec<<<GRID_R, 128>>>(0, h0, c0, Whh0,
                              hs0_p, nullptr, hT, cT);
    // layer 1 (input = layer-0 hidden states)
    xg_gemm<<<ggrid, 256>>>(hs0_p, Wih1, b1v, xg_p);
    lstm_rec<<<GRID_R, 128>>>(1, h0 + BB * HH, c0 + BB * HH, Whh1,
                              hs_final, cs_final, hT + BB * HH, cT + BB * HH);
}

// round 9
// speedup vs baseline: 1.4327x; 1.4327x over previous
#include <cuda_runtime.h>

#define TT 2048
#define BB 32
#define HH 256
#define G4H 1024
#define GRID_R 128

// ---------------- scratch (static device allocations; no cudaMalloc) ----------------
__device__ float g_xg[(size_t)TT * G4H * BB];   // [t][gate_row][b]  256 MB
__device__ float g_hs0[(size_t)TT * BB * HH];   // layer-0 hidden outputs, 64 MB
__device__ float g_hbuf[2][BB * HH];            // double-buffered h state [buf][b][j]
__device__ unsigned g_ctrs[2][8 * 32];          // distributed arrival counters (128B apart)
__device__ unsigned g_epoch[2][4 * 32];         // epoch flag, replicated x4 (128B apart)
__device__ unsigned g_done[2];                  // per-layer reset handshake
__device__ int g_len[BB];                       // normalized lengths (int32)

// morally-strong memory helpers (gpu scope)
__device__ __forceinline__ void arrive_release(unsigned* p) {
    asm volatile("red.release.gpu.global.add.u32 [%0], %1;" :: "l"(p), "r"(1u) : "memory");
}
__device__ __forceinline__ unsigned ld_relaxed(const unsigned* p) {
    unsigned v;
    asm volatile("ld.relaxed.gpu.global.u32 %0, [%1];" : "=r"(v) : "l"(p) : "memory");
    return v;
}
__device__ __forceinline__ void st_relaxed(unsigned* p, unsigned v) {
    asm volatile("st.relaxed.gpu.global.u32 [%0], %1;" :: "l"(p), "r"(v) : "memory");
}

// ---------------- lengths normalization: handles int32 OR int64 input buffer ----------
__global__ void norm_lengths(const int* __restrict__ lenw)
{
    int i = threadIdx.x;            // 0..31
    int is64 = (lenw[1] == 0);
    int v = is64 ? lenw[2 * i] : lenw[i];
    g_len[i] = v;
}

// ---------------- input-projection GEMM: out[t][row][b] = X @ W^T + bias ----------------
// X: [T*B][256] row-major, W: [1024][256], out: [T][1024][32]
__global__ __launch_bounds__(256) void xg_gemm(const float* __restrict__ X,
                                               const float* __restrict__ W,
                                               const float* __restrict__ bias,
                                               float* __restrict__ out)
{
    __shared__ float xs[64][65];
    __shared__ float ws[64][65];
    const int tid = threadIdx.x;
    const int tx = tid & 15;        // tb quad
    const int ty = tid >> 4;        // row quad
    const int tb0 = blockIdx.x * 64;
    const int r0 = blockIdx.y * 64;
    const int lrow = tid >> 4;      // load row 0..15 (x4 passes)
    const int lkq = tid & 15;       // load k-quad

    float acc[4][4];
#pragma unroll
    for (int i = 0; i < 4; i++)
#pragma unroll
        for (int j = 0; j < 4; j++) acc[i][j] = 0.f;

    for (int kt = 0; kt < 256; kt += 64) {
#pragma unroll
        for (int p = 0; p < 4; p++) {
            int row = lrow + p * 16;
            float4 xv = *(const float4*)&X[(size_t)(tb0 + row) * 256 + kt + lkq * 4];
            xs[row][lkq * 4 + 0] = xv.x; xs[row][lkq * 4 + 1] = xv.y;
            xs[row][lkq * 4 + 2] = xv.z; xs[row][lkq * 4 + 3] = xv.w;
            float4 wv = *(const float4*)&W[(size_t)(r0 + row) * 256 + kt + lkq * 4];
            ws[row][lkq * 4 + 0] = wv.x; ws[row][lkq * 4 + 1] = wv.y;
            ws[row][lkq * 4 + 2] = wv.z; ws[row][lkq * 4 + 3] = wv.w;
        }
        __syncthreads();
#pragma unroll 8
        for (int k = 0; k < 64; k++) {
            float xf[4], wf[4];
#pragma unroll
            for (int j = 0; j < 4; j++) xf[j] = xs[tx * 4 + j][k];
#pragma unroll
            for (int i = 0; i < 4; i++) wf[i] = ws[ty * 4 + i][k];
#pragma unroll
            for (int i = 0; i < 4; i++)
#pragma unroll
                for (int j = 0; j < 4; j++) acc[i][j] += wf[i] * xf[j];
        }
        __syncthreads();
    }

    const int tbb = tb0 + tx * 4;
    const int t = tbb >> 5;
    const int b0 = tbb & 31;
#pragma unroll
    for (int i = 0; i < 4; i++) {
        int row = r0 + ty * 4 + i;
        float bv = bias[row];
        float4 v = make_float4(acc[i][0] + bv, acc[i][1] + bv, acc[i][2] + bv, acc[i][3] + bv);
        *(float4*)&out[(size_t)t * 32768 + row * 32 + b0] = v;
    }
}

// ---------------- persistent recurrent kernel (one layer) ----------------
// 128 threads: b = tid&31, w = tid>>5 (0..3). Thread computes rows q=w and q=w+4
// (q -> gate = q>>1, u = q&1). CTA owns units {2*bid, 2*bid+1}; 128 CTAs.
// Barrier: release-arrivals to 8 distributed counters; CTA0 aggregator polls them
// with RELAXED ATOMIC loads (morally strong, MLP=8), fences (acquire pattern),
// publishes a x4-replicated epoch with relaxed atomic stores (release pattern after
// the fence); followers relaxed-poll one replica + fence. Formally correct chain
// with pipelined polls. Per-step output stores happen AFTER the arrival.
__global__ __launch_bounds__(128) void lstm_rec(
    const int layer,
    const float* __restrict__ h0,        // [B][H] slice for this layer
    const float* __restrict__ c0,
    const float* __restrict__ Whh,       // [1024][256]
    float* __restrict__ hs_out,          // [T][B][H]
    float* __restrict__ cs_out,          // [T][B][H] or nullptr
    float* __restrict__ hT_out,          // [B][H]
    float* __restrict__ cT_out)
{
    __shared__ float4 w4s[8 * 64];        // 8 gate rows x 256 k (float4)
    __shared__ float4 h4s[32 * 65];       // h staged [b][k4], pitch 65 -> conflict-free
    __shared__ float gsm[8][33];          // gate exchange

    const int tid = threadIdx.x;
    const int b = tid & 31;
    const int w = tid >> 5;               // 0..3
    const int bid = blockIdx.x;
    const int row0 = (w >> 1) * 256 + bid * 2 + (w & 1);
    const int row1 = row0 + 512;

    // load this CTA's 8 W_hh rows into smem (once)
    {
        const float4* W4 = (const float4*)Whh;
#pragma unroll
        for (int p = 0; p < 4; p++) {
            int i = tid + p * 128;        // 0..511
            int qq = i >> 6, k4 = i & 63;
            int rr = (qq >> 1) * 256 + bid * 2 + (qq & 1);
            w4s[i] = W4[(size_t)rr * 64 + k4];
        }
    }

    // state owners: tid < 64 -> (u = tid>>5, b)
    float c_reg = 0.f, h_reg = 0.f;
    int len_b = 0;
    const int j_own = bid * 2 + (tid >> 5);   // valid for tid<64
    if (tid < 64) {
        h_reg = h0[b * 256 + j_own];
        c_reg = c0[b * 256 + j_own];
        len_b = g_len[b];
        __stcg(&g_hbuf[0][b * 256 + j_own], h_reg);
    }
    __threadfence();
    __syncthreads();
    if (tid == 0) arrive_release(&g_ctrs[layer][(bid & 7) * 32]);

    unsigned target = GRID_R;

    for (int t = 0; t < TT; t++) {
        // prefetch xg (independent of barrier) to hide DRAM latency behind sync
        float xg0 = __ldg(&g_xg[(size_t)t * 32768 + row0 * 32 + b]);
        float xg1 = __ldg(&g_xg[(size_t)t * 32768 + row1 * 32 + b]);

        if (tid == 0) {
            if (bid == 0) {
                // aggregator: 8 relaxed atomic loads per poll (pipelined, MLP=8)
                unsigned* cp = &g_ctrs[layer][0];
                unsigned s;
                do {
                    unsigned v0 = ld_relaxed(cp + 0 * 32);
                    unsigned v1 = ld_relaxed(cp + 1 * 32);
                    unsigned v2 = ld_relaxed(cp + 2 * 32);
                    unsigned v3 = ld_relaxed(cp + 3 * 32);
                    unsigned v4 = ld_relaxed(cp + 4 * 32);
                    unsigned v5 = ld_relaxed(cp + 5 * 32);
                    unsigned v6 = ld_relaxed(cp + 6 * 32);
                    unsigned v7 = ld_relaxed(cp + 7 * 32);
                    s = v0 + v1 + v2 + v3 + v4 + v5 + v6 + v7;
                } while (s < target);
                __threadfence();   // acquire (obs. arrivals) + release (for epoch)
                unsigned e = (unsigned)(t + 1);
                st_relaxed(&g_epoch[layer][0 * 32], e);
                st_relaxed(&g_epoch[layer][1 * 32], e);
                st_relaxed(&g_epoch[layer][2 * 32], e);
                st_relaxed(&g_epoch[layer][3 * 32], e);
            } else {
                // follower: relaxed atomic poll of one epoch replica
                const unsigned* ep = &g_epoch[layer][(bid & 3) * 32];
                while (ld_relaxed(ep) < (unsigned)(t + 1)) { }
                __threadfence();   // acquire pattern: epoch obs -> h visibility
            }
        }
        __syncthreads();
        target += GRID_R;

        // stage full h into smem (L2-coherent loads; cross-SM producer)
        {
            const float4* hb = (const float4*)g_hbuf[t & 1];
#pragma unroll
            for (int p = 0; p < 16; p++) {
                int i = tid + p * 128;    // 0..2047
                h4s[(i >> 6) * 65 + (i & 63)] = __ldcg(&hb[i]);
            }
        }
        __syncthreads();

        // dot: two rows per thread, hv reused; wv loads are warp-broadcast
        float a0 = 0.f, a1 = 0.f;
        {
            const float4* hr = &h4s[b * 65];
            const float4* w0 = &w4s[w * 64];
            const float4* w1 = &w4s[(w + 4) * 64];
#pragma unroll 16
            for (int k4 = 0; k4 < 64; k4++) {
                float4 hv = hr[k4];
                float4 v0 = w0[k4];
                float4 v1 = w1[k4];
                a0 += hv.x * v0.x; a0 += hv.y * v0.y;
                a0 += hv.z * v0.z; a0 += hv.w * v0.w;
                a1 += hv.x * v1.x; a1 += hv.y * v1.y;
                a1 += hv.z * v1.z; a1 += hv.w * v1.w;
            }
        }
        gsm[w][b] = a0 + xg0;
        gsm[w + 4][b] = a1 + xg1;
        __syncthreads();

        float hs_val = 0.f, cs_val = 0.f;
        if (tid < 64) {
            int u = tid >> 5;
            float gi = gsm[0 + u][b];
            float gf = gsm[2 + u][b];
            float gg = gsm[4 + u][b];
            float go = gsm[6 + u][b];
            float i_ = 1.f / (1.f + __expf(-gi));
            float f_ = 1.f / (1.f + __expf(-gf));
            float g_ = tanhf(gg);
            float o_ = 1.f / (1.f + __expf(-go));
            float cn = f_ * c_reg + i_ * g_;
            float hn = o_ * tanhf(cn);
            if (t < len_b) { c_reg = cn; h_reg = hn; }
            __stcg(&g_hbuf[(t + 1) & 1][b * 256 + j_own], h_reg);
            hs_val = h_reg; cs_val = c_reg;
        }
        __syncthreads();
        if (tid == 0) arrive_release(&g_ctrs[layer][(bid & 7) * 32]);

        // output stores AFTER arrival: overlap with other CTAs' barrier wait
        if (tid < 64) {
            int oidx = t * 8192 + b * 256 + j_own;
            hs_out[oidx] = hs_val;
            if (cs_out) cs_out[oidx] = cs_val;
        }
    }

    if (tid < 64) {
        hT_out[b * 256 + j_own] = h_reg;
        cT_out[b * 256 + j_own] = c_reg;
    }

    // reset handshake so graph replays start from clean counters.
    // Fence between the final arrival atomic and the g_done atomic (closes the
    // cross-L2-slice reset race; verified fix in round 7).
    __syncthreads();
    if (tid == 0) {
        __threadfence();
        unsigned d = atomicAdd(&g_done[layer], 1);
        if (d == GRID_R - 1) {
#pragma unroll
            for (int i = 0; i < 8; i++) g_ctrs[layer][i * 32] = 0;
#pragma unroll
            for (int i = 0; i < 4; i++) g_epoch[layer][i * 32] = 0;
            __threadfence();
            g_done[layer] = 0;
        }
    }
}

// ---------------- launch ----------------
extern "C" void kernel_launch(void* const* d_in, const int* in_sizes, int n_in,
                              void* d_out, int out_size)
{
    const float* x        = (const float*)d_in[0];
    const int*   lenw     = (const int*)d_in[1];   // dtype detected on device
    const float* h0       = (const float*)d_in[2];
    const float* c0       = (const float*)d_in[3];
    const float* Wih0     = (const float*)d_in[4];
    const float* Whh0     = (const float*)d_in[5];
    const float* b0v      = (const float*)d_in[6];
    const float* Wih1     = (const float*)d_in[7];
    const float* Whh1     = (const float*)d_in[8];
    const float* b1v      = (const float*)d_in[9];
    float* out = (float*)d_out;

    float* xg_p = nullptr;
    float* hs0_p = nullptr;
    cudaGetSymbolAddress((void**)&xg_p, g_xg);
    cudaGetSymbolAddress((void**)&hs0_p, g_hs0);

    const size_t SEQ = (size_t)TT * BB * HH;   // 16,777,216
    float* hs_final = out;                     // [T][B][H]
    float* cs_final = out + SEQ;               // [T][B][H]
    float* hT = out + 2 * SEQ;                 // [2][B][H]
    float* cT = out + 2 * SEQ + 2 * BB * HH;   // [2][B][H]

    dim3 ggrid(1024, 16);

    norm_lengths<<<1, 32>>>(lenw);

    // layer 0
    xg_gemm<<<ggrid, 256>>>(x, Wih0, b0v, xg_p);
    lstm_rec<<<GRID_R, 128>>>(0, h0, c0, Whh0,
                              hs0_p, nullptr, hT, cT);
    // layer 1 (input = layer-0 hidden states)
    xg_gemm<<<ggrid, 256>>>(hs0_p, Wih1, b1v, xg_p);
    lstm_rec<<<GRID_R, 128>>>(1, h0 + BB * HH, c0 + BB * HH, Whh1,
                              hs_final, cs_final, hT + BB * HH, cT + BB * HH);
}

// round 10
// speedup vs baseline: 2.1265x; 1.4842x over previous
#include <cuda_runtime.h>

#define TT 2048
#define BB 32
#define HH 256
#define G4H 1024
#define GRID_R 128
#define CPG 8          // CTAs per group
#define NGRP 16        // groups (2 batches each)

// ---------------- scratch (static device allocations; no cudaMalloc) ----------------
__device__ float g_xg[(size_t)TT * G4H * BB];     // [t][gate_row][b]  256 MB
__device__ float g_hs0[(size_t)TT * BB * HH];     // layer-0 hidden outputs, 64 MB
__device__ float g_hx[NGRP][2][2][HH];            // h exchange [group][buf][lb][j]
__device__ unsigned g_gctr[2][NGRP][32];          // per-layer per-group counters (128B lines)
__device__ unsigned g_done[2];                    // per-layer reset handshake
__device__ int g_len[BB];                         // normalized lengths (int32)

// morally-strong memory helpers (gpu scope)
__device__ __forceinline__ void arrive_release(unsigned* p) {
    asm volatile("red.release.gpu.global.add.u32 [%0], %1;" :: "l"(p), "r"(1u) : "memory");
}
__device__ __forceinline__ unsigned ld_relaxed(const unsigned* p) {
    unsigned v;
    asm volatile("ld.relaxed.gpu.global.u32 %0, [%1];" : "=r"(v) : "l"(p) : "memory");
    return v;
}

// ---------------- lengths normalization: handles int32 OR int64 input buffer ----------
__global__ void norm_lengths(const int* __restrict__ lenw)
{
    int i = threadIdx.x;            // 0..31
    int is64 = (lenw[1] == 0);
    int v = is64 ? lenw[2 * i] : lenw[i];
    g_len[i] = v;
}

// ---------------- input-projection GEMM: out[t][row][b] = X @ W^T + bias ----------------
// X: [T*B][256] row-major, W: [1024][256], out: [T][1024][32]
__global__ __launch_bounds__(256) void xg_gemm(const float* __restrict__ X,
                                               const float* __restrict__ W,
                                               const float* __restrict__ bias,
                                               float* __restrict__ out)
{
    __shared__ float xs[64][65];
    __shared__ float ws[64][65];
    const int tid = threadIdx.x;
    const int tx = tid & 15;        // tb quad
    const int ty = tid >> 4;        // row quad
    const int tb0 = blockIdx.x * 64;
    const int r0 = blockIdx.y * 64;
    const int lrow = tid >> 4;      // load row 0..15 (x4 passes)
    const int lkq = tid & 15;       // load k-quad

    float acc[4][4];
#pragma unroll
    for (int i = 0; i < 4; i++)
#pragma unroll
        for (int j = 0; j < 4; j++) acc[i][j] = 0.f;

    for (int kt = 0; kt < 256; kt += 64) {
#pragma unroll
        for (int p = 0; p < 4; p++) {
            int row = lrow + p * 16;
            float4 xv = *(const float4*)&X[(size_t)(tb0 + row) * 256 + kt + lkq * 4];
            xs[row][lkq * 4 + 0] = xv.x; xs[row][lkq * 4 + 1] = xv.y;
            xs[row][lkq * 4 + 2] = xv.z; xs[row][lkq * 4 + 3] = xv.w;
            float4 wv = *(const float4*)&W[(size_t)(r0 + row) * 256 + kt + lkq * 4];
            ws[row][lkq * 4 + 0] = wv.x; ws[row][lkq * 4 + 1] = wv.y;
            ws[row][lkq * 4 + 2] = wv.z; ws[row][lkq * 4 + 3] = wv.w;
        }
        __syncthreads();
#pragma unroll 8
        for (int k = 0; k < 64; k++) {
            float xf[4], wf[4];
#pragma unroll
            for (int j = 0; j < 4; j++) xf[j] = xs[tx * 4 + j][k];
#pragma unroll
            for (int i = 0; i < 4; i++) wf[i] = ws[ty * 4 + i][k];
#pragma unroll
            for (int i = 0; i < 4; i++)
#pragma unroll
                for (int j = 0; j < 4; j++) acc[i][j] += wf[i] * xf[j];
        }
        __syncthreads();
    }

    const int tbb = tb0 + tx * 4;
    const int t = tbb >> 5;
    const int b0 = tbb & 31;
#pragma unroll
    for (int i = 0; i < 4; i++) {
        int row = r0 + ty * 4 + i;
        float bv = bias[row];
        float4 v = make_float4(acc[i][0] + bv, acc[i][1] + bv, acc[i][2] + bv, acc[i][3] + bv);
        *(float4*)&out[(size_t)t * 32768 + row * 32 + b0] = v;
    }
}

// ---------------- persistent recurrent kernel: GROUP-LOCAL sync ----------------
// 128 CTAs = 16 groups x 8 CTAs. Group g owns batches {2g, 2g+1}. CTA r in group
// holds W_hh rows {256*G + 32*r + jj : G in 0..3, jj in 0..31} in smem (130KB) and
// computes those 128 gate rows for both batches. Sync: one counter line per group,
// 8 release-arrivals + 8 relaxed pollers + fence. h exchanged via 2KB L2 buffer,
// double-buffered across steps. No global barrier anywhere.
__global__ __launch_bounds__(256) void lstm_rec(
    const int layer,
    const float* __restrict__ h0,        // [B][H] slice for this layer
    const float* __restrict__ c0,
    const float* __restrict__ Whh,       // [1024][256]
    float* __restrict__ hs_out,          // [T][B][H]
    float* __restrict__ cs_out,          // [T][B][H] or nullptr
    float* __restrict__ hT_out,          // [B][H]
    float* __restrict__ cT_out)
{
    extern __shared__ float smem[];
    // layout: sw[128][260] | hsm[2][260] | gsm[256]
    float* sw  = smem;                    // W rows, pitch 260 (conflict-free)
    float* hsm = smem + 128 * 260;        // staged h, pitch 260
    float* gsm = hsm + 2 * 260;           // gate exchange, gsm[rl*2+lb]

    const int tid = threadIdx.x;          // 0..255
    const int bid = blockIdx.x;           // 0..127
    const int g   = bid >> 3;             // group
    const int r   = bid & 7;              // rank in group
    const int rl  = tid >> 1;             // row_local 0..127
    const int lb  = tid & 1;              // local batch 0/1
    const int grow = (rl >> 5) * 256 + r * 32 + (rl & 31);  // global gate row
    const int bglob = 2 * g + lb;

    // load this CTA's 128 W_hh rows into smem (once)
    for (int i = tid; i < 128 * 256; i += 256) {
        int row = i >> 8, k = i & 255;
        int grr = 256 * (row >> 5) + 32 * r + (row & 31);
        sw[row * 260 + k] = Whh[(size_t)grr * 256 + k];
    }

    // state owners: tid < 64 -> (jj_o = tid>>1, b_o = tid&1)
    const int jj_o = tid >> 1;            // unit within CTA's 32 (valid tid<64)
    const int b_o  = tid & 1;
    const int j_o  = 32 * r + jj_o;       // global unit
    const int bg_o = 2 * g + b_o;

    float c_reg = 0.f, h_reg = 0.f;
    int len_b = 0;
    if (tid < 64) {
        h_reg = h0[bg_o * 256 + j_o];
        c_reg = c0[bg_o * 256 + j_o];
        len_b = g_len[bg_o];
        __stcg(&g_hx[g][0][b_o][j_o], h_reg);
    }
    __syncthreads();
    if (tid == 0) arrive_release(&g_gctr[layer][g][0]);

    unsigned target = CPG;

    for (int t = 0; t < TT; t++) {
        // prefetch xg (independent of barrier)
        float xgv = __ldg(&g_xg[(size_t)t * 32768 + grow * 32 + bglob]);

        // group barrier: 8 arrivals, everyone polls own group's line
        if (tid == 0) {
            const unsigned* cp = &g_gctr[layer][g][0];
            while (ld_relaxed(cp) < target) { }
            __threadfence();   // acquire: counter obs -> peer h visibility
        }
        __syncthreads();
        target += CPG;

        // stage group h (2 batches x 256) into smem
        if (tid < 128) {
            const float4* hb = (const float4*)&g_hx[g][t & 1][0][0];
            float4 v = __ldcg(&hb[tid]);
            int b_ = tid >> 6, k4 = tid & 63;
            *(float4*)&hsm[b_ * 260 + k4 * 4] = v;
        }
        __syncthreads();

        // dot: thread (rl, lb): gates[grow][bglob] = xg + W_row . h[lb]
        float a = 0.f;
        {
            const float4* wr = (const float4*)&sw[rl * 260];
            const float4* hr = (const float4*)&hsm[lb * 260];
#pragma unroll 16
            for (int k4 = 0; k4 < 64; k4++) {
                float4 wv = wr[k4];
                float4 hv = hr[k4];
                a += wv.x * hv.x; a += wv.y * hv.y;
                a += wv.z * hv.z; a += wv.w * hv.w;
            }
        }
        gsm[tid] = a + xgv;               // gsm[rl*2 + lb]
        __syncthreads();

        float hs_val = 0.f, cs_val = 0.f;
        if (tid < 64) {
            float gi = gsm[(jj_o) * 2 + b_o];            // G=0 rows
            float gf = gsm[(32 + jj_o) * 2 + b_o];       // G=1
            float gg = gsm[(64 + jj_o) * 2 + b_o];       // G=2
            float go = gsm[(96 + jj_o) * 2 + b_o];       // G=3
            float i_ = 1.f / (1.f + __expf(-gi));
            float f_ = 1.f / (1.f + __expf(-gf));
            float g_ = tanhf(gg);
            float o_ = 1.f / (1.f + __expf(-go));
            float cn = f_ * c_reg + i_ * g_;
            float hn = o_ * tanhf(cn);
            if (t < len_b) { c_reg = cn; h_reg = hn; }
            __stcg(&g_hx[g][(t + 1) & 1][b_o][j_o], h_reg);
            hs_val = h_reg; cs_val = c_reg;
        }
        __syncthreads();
        if (tid == 0) arrive_release(&g_gctr[layer][g][0]);

        // output stores AFTER arrival (host-consumed only; overlap peers' wait)
        if (tid < 64) {
            int oidx = t * 8192 + bg_o * 256 + j_o;
            hs_out[oidx] = hs_val;
            if (cs_out) cs_out[oidx] = cs_val;
        }
    }

    if (tid < 64) {
        hT_out[bg_o * 256 + j_o] = h_reg;
        cT_out[bg_o * 256 + j_o] = c_reg;
    }

    // reset handshake so graph replays start from clean counters.
    // Fence between final arrival atomic and g_done atomic (verified round-7 fix).
    __syncthreads();
    if (tid == 0) {
        __threadfence();
        unsigned d = atomicAdd(&g_done[layer], 1);
        if (d == GRID_R - 1) {
#pragma unroll
            for (int i = 0; i < NGRP; i++) g_gctr[layer][i][0] = 0;
            __threadfence();
            g_done[layer] = 0;
        }
    }
}

// ---------------- launch ----------------
extern "C" void kernel_launch(void* const* d_in, const int* in_sizes, int n_in,
                              void* d_out, int out_size)
{
    const float* x        = (const float*)d_in[0];
    const int*   lenw     = (const int*)d_in[1];   // dtype detected on device
    const float* h0       = (const float*)d_in[2];
    const float* c0       = (const float*)d_in[3];
    const float* Wih0     = (const float*)d_in[4];
    const float* Whh0     = (const float*)d_in[5];
    const float* b0v      = (const float*)d_in[6];
    const float* Wih1     = (const float*)d_in[7];
    const float* Whh1     = (const float*)d_in[8];
    const float* b1v      = (const float*)d_in[9];
    float* out = (float*)d_out;

    float* xg_p = nullptr;
    float* hs0_p = nullptr;
    cudaGetSymbolAddress((void**)&xg_p, g_xg);
    cudaGetSymbolAddress((void**)&hs0_p, g_hs0);

    const size_t SEQ = (size_t)TT * BB * HH;   // 16,777,216
    float* hs_final = out;                     // [T][B][H]
    float* cs_final = out + SEQ;               // [T][B][H]
    float* hT = out + 2 * SEQ;                 // [2][B][H]
    float* cT = out + 2 * SEQ + 2 * BB * HH;   // [2][B][H]

    // dynamic smem for lstm_rec: (128*260 + 2*260 + 256) floats
    const int rec_smem = (128 * 260 + 2 * 260 + 256) * (int)sizeof(float);
    cudaFuncSetAttribute(lstm_rec, cudaFuncAttributeMaxDynamicSharedMemorySize, rec_smem);

    dim3 ggrid(1024, 16);

    norm_lengths<<<1, 32>>>(lenw);

    // layer 0
    xg_gemm<<<ggrid, 256>>>(x, Wih0, b0v, xg_p);
    lstm_rec<<<GRID_R, 256, rec_smem>>>(0, h0, c0, Whh0,
                                        hs0_p, nullptr, hT, cT);
    // layer 1 (input = layer-0 hidden states)
    xg_gemm<<<ggrid, 256>>>(hs0_p, Wih1, b1v, xg_p);
    lstm_rec<<<GRID_R, 256, rec_smem>>>(1, h0 + BB * HH, c0 + BB * HH, Whh1,
                                        hs_final, cs_final, hT + BB * HH, cT + BB * HH);
}